// round 3
// baseline (speedup 1.0000x reference)
#include <cuda_runtime.h>
#include <math.h>

// Problem constants (fixed shapes)
#define T_TOK 4096
#define DIM   512
#define FDIM  1024
#define NE    8
#define TOPK  2
#define NPAIR (T_TOK*TOPK)

// ---------------- device scratch (static; no runtime allocation) ----------------
__device__ int   g_cnt[NE];
__device__ int   g_list[NE*T_TOK];   // packed (token<<1)|k
__device__ float g_wgt [NE*T_TOK];   // normalized top-k weight for that pair
__device__ float g_sumP[NE];
__device__ float g_zsum;
__device__ float g_hidden[(size_t)NPAIR*FDIM];  // silu(g)*u per pair  (33.5 MB)
__device__ float g_pout [(size_t)NPAIR*DIM];    // per-pair down-proj   (16.8 MB)

// ---------------- f32x2 packed-FMA helpers (sm_100+ PTX) ----------------
__device__ __forceinline__ unsigned long long pack2(float lo, float hi) {
    unsigned long long r;
    asm("mov.b64 %0, {%1, %2};" : "=l"(r) : "f"(lo), "f"(hi));
    return r;
}
__device__ __forceinline__ float2 unpack2(unsigned long long v) {
    float2 r;
    asm("mov.b64 {%0, %1}, %2;" : "=f"(r.x), "=f"(r.y) : "l"(v));
    return r;
}
__device__ __forceinline__ void ffma2(unsigned long long& acc,
                                      unsigned long long a, unsigned long long b) {
    asm("fma.rn.f32x2 %0, %1, %2, %0;" : "+l"(acc) : "l"(a), "l"(b));
}

// ---------------- zero per-launch accumulators ----------------
__global__ void zero_kernel() {
    int i = threadIdx.x;
    if (i < NE) { g_cnt[i] = 0; g_sumP[i] = 0.f; }
    if (i == 0) g_zsum = 0.f;
}

// ---------------- router: logits, softmax, top-2, lists, aux sums ----------------
__global__ void router_kernel(const float* __restrict__ x, const float* __restrict__ rw) {
    int gw   = (blockIdx.x * blockDim.x + threadIdx.x) >> 5;   // token
    int lane = threadIdx.x & 31;
    if (gw >= T_TOK) return;

    const float4* xp = (const float4*)(x + (size_t)gw * DIM);
    float4 xv[4];
#pragma unroll
    for (int i = 0; i < 4; i++) xv[i] = xp[lane * 4 + i];

    float logit[NE];
#pragma unroll
    for (int e = 0; e < NE; e++) {
        const float4* wp = (const float4*)(rw + (size_t)e * DIM);
        float acc = 0.f;
#pragma unroll
        for (int i = 0; i < 4; i++) {
            float4 w4 = wp[lane * 4 + i];
            acc += xv[i].x * w4.x + xv[i].y * w4.y + xv[i].z * w4.z + xv[i].w * w4.w;
        }
#pragma unroll
        for (int o = 16; o > 0; o >>= 1) acc += __shfl_xor_sync(0xffffffffu, acc, o);
        logit[e] = acc;
    }

    if (lane == 0) {
        float m = logit[0];
#pragma unroll
        for (int e = 1; e < NE; e++) m = fmaxf(m, logit[e]);
        float p[NE]; float se = 0.f;
#pragma unroll
        for (int e = 0; e < NE; e++) { p[e] = expf(logit[e] - m); se += p[e]; }
        float inv = 1.f / se;

        int i0 = 0; float v0 = -1.f;
#pragma unroll
        for (int e = 0; e < NE; e++) if (p[e] > v0) { v0 = p[e]; i0 = e; }
        int i1 = -1; float v1 = -1.f;
#pragma unroll
        for (int e = 0; e < NE; e++) if (e != i0 && p[e] > v1) { v1 = p[e]; i1 = e; }

        float s2 = v0 + v1;
        float w0 = v0 / s2, w1 = v1 / s2;

        int pos0 = atomicAdd(&g_cnt[i0], 1);
        g_list[i0 * T_TOK + pos0] = (gw << 1);
        g_wgt [i0 * T_TOK + pos0] = w0;
        int pos1 = atomicAdd(&g_cnt[i1], 1);
        g_list[i1 * T_TOK + pos1] = (gw << 1) | 1;
        g_wgt [i1 * T_TOK + pos1] = w1;

#pragma unroll
        for (int e = 0; e < NE; e++) atomicAdd(&g_sumP[e], p[e] * inv);
        float lse = m + logf(se);
        atomicAdd(&g_zsum, lse * lse);
    }
}

// ---------------- phase A: hidden = silu(Xe@gate) * (Xe@up), gathered rows ----------------
#define BMA 128
#define BNA 64
#define BKA 16
__global__ void __launch_bounds__(256) gateup_kernel(const float* __restrict__ x,
                                                     const float* __restrict__ gw,
                                                     const float* __restrict__ uw) {
    int e = blockIdx.z;
    int cnt = g_cnt[e];
    int row0 = blockIdx.y * BMA;
    if (row0 >= cnt) return;
    int col0 = blockIdx.x * BNA;

    __shared__ __align__(16) float sA [BKA][BMA];
    __shared__ __align__(16) float sBg[BKA][BNA];
    __shared__ __align__(16) float sBu[BKA][BNA];
    __shared__ int sTok[BMA];

    int tid = threadIdx.x;
    for (int i = tid; i < BMA; i += 256) {
        int r = row0 + i;
        sTok[i] = (r < cnt) ? g_list[e * T_TOK + r] : -1;
    }
    __syncthreads();

    int tx = tid & 15, ty = tid >> 4;
    unsigned long long accg[8][2], accu[8][2];
#pragma unroll
    for (int i = 0; i < 8; i++) {
        accg[i][0] = accg[i][1] = 0ull;
        accu[i][0] = accu[i][1] = 0ull;
    }

    const float* gbase = gw + (size_t)e * DIM * FDIM + col0;
    const float* ubase = uw + (size_t)e * DIM * FDIM + col0;

    int ra = tid >> 1;           // 0..127  A row
    int ca = (tid & 1) * 8;      // 0 / 8   A col block
    int entryA = sTok[ra];
    const float* xrow = (entryA >= 0) ? (x + (size_t)(entryA >> 1) * DIM) : x;
    int kb  = tid >> 4;          // 0..15   B row
    int cb  = (tid & 15) * 4;    // B col

    for (int kt = 0; kt < DIM; kt += BKA) {
        float4 a0, a1;
        if (entryA >= 0) {
            a0 = *(const float4*)(xrow + kt + ca);
            a1 = *(const float4*)(xrow + kt + ca + 4);
        } else {
            a0 = make_float4(0.f,0.f,0.f,0.f); a1 = a0;
        }
        float4 bg4 = *(const float4*)(gbase + (size_t)(kt + kb) * FDIM + cb);
        float4 bu4 = *(const float4*)(ubase + (size_t)(kt + kb) * FDIM + cb);
        __syncthreads();
        sA[ca+0][ra] = a0.x; sA[ca+1][ra] = a0.y; sA[ca+2][ra] = a0.z; sA[ca+3][ra] = a0.w;
        sA[ca+4][ra] = a1.x; sA[ca+5][ra] = a1.y; sA[ca+6][ra] = a1.z; sA[ca+7][ra] = a1.w;
        *(float4*)&sBg[kb][cb] = bg4;
        *(float4*)&sBu[kb][cb] = bu4;
        __syncthreads();

#pragma unroll
        for (int kk = 0; kk < BKA; kk++) {
            float4 av0 = *(const float4*)&sA[kk][ty * 8];
            float4 av1 = *(const float4*)&sA[kk][ty * 8 + 4];
            float4 bg  = *(const float4*)&sBg[kk][tx * 4];
            float4 bu  = *(const float4*)&sBu[kk][tx * 4];
            unsigned long long bg01 = pack2(bg.x, bg.y), bg23 = pack2(bg.z, bg.w);
            unsigned long long bu01 = pack2(bu.x, bu.y), bu23 = pack2(bu.z, bu.w);
            float a[8] = {av0.x, av0.y, av0.z, av0.w, av1.x, av1.y, av1.z, av1.w};
#pragma unroll
            for (int i = 0; i < 8; i++) {
                unsigned long long aa = pack2(a[i], a[i]);
                ffma2(accg[i][0], aa, bg01);
                ffma2(accg[i][1], aa, bg23);
                ffma2(accu[i][0], aa, bu01);
                ffma2(accu[i][1], aa, bu23);
            }
        }
    }

#pragma unroll
    for (int i = 0; i < 8; i++) {
        int r = ty * 8 + i;
        int entry = sTok[r];
        if (entry < 0) continue;
        float2 g0 = unpack2(accg[i][0]), g1 = unpack2(accg[i][1]);
        float2 u0 = unpack2(accu[i][0]), u1 = unpack2(accu[i][1]);
        float4 h;
        h.x = u0.x * (g0.x / (1.f + expf(-g0.x)));
        h.y = u0.y * (g0.y / (1.f + expf(-g0.y)));
        h.z = u1.x * (g1.x / (1.f + expf(-g1.x)));
        h.w = u1.y * (g1.y / (1.f + expf(-g1.y)));
        *(float4*)(g_hidden + (size_t)entry * FDIM + col0 + tx * 4) = h;
    }
}

// ---------------- phase B: pair_out = w * (hidden @ down) ----------------
#define BMB 128
#define BNB 128
#define BKB 16
__global__ void __launch_bounds__(256) down_kernel(const float* __restrict__ dw) {
    int e = blockIdx.z;
    int cnt = g_cnt[e];
    int row0 = blockIdx.y * BMB;
    if (row0 >= cnt) return;
    int col0 = blockIdx.x * BNB;

    __shared__ __align__(16) float sA[BKB][BMB];
    __shared__ __align__(16) float sB[BKB][BNB];
    __shared__ int   sTok[BMB];
    __shared__ float sW  [BMB];

    int tid = threadIdx.x;
    for (int i = tid; i < BMB; i += 256) {
        int r = row0 + i;
        sTok[i] = (r < cnt) ? g_list[e * T_TOK + r] : -1;
        sW[i]   = (r < cnt) ? g_wgt [e * T_TOK + r] : 0.f;
    }
    __syncthreads();

    int tx = tid & 15, ty = tid >> 4;
    unsigned long long acc[8][4];
#pragma unroll
    for (int i = 0; i < 8; i++)
#pragma unroll
        for (int j = 0; j < 4; j++) acc[i][j] = 0ull;

    int ra = tid >> 1;         // A row
    int ca = (tid & 1) * 8;
    int entryA = sTok[ra];
    const float* hrow = (entryA >= 0) ? (g_hidden + (size_t)entryA * FDIM) : g_hidden;
    int kb  = tid >> 4;        // 0..15 B row
    int cbB = (tid & 15) * 8;  // B col
    const float* dbase = dw + (size_t)e * FDIM * DIM + col0;

    for (int kt = 0; kt < FDIM; kt += BKB) {
        float4 a0, a1;
        if (entryA >= 0) {
            a0 = *(const float4*)(hrow + kt + ca);
            a1 = *(const float4*)(hrow + kt + ca + 4);
        } else {
            a0 = make_float4(0.f,0.f,0.f,0.f); a1 = a0;
        }
        float4 b0 = *(const float4*)(dbase + (size_t)(kt + kb) * DIM + cbB);
        float4 b1 = *(const float4*)(dbase + (size_t)(kt + kb) * DIM + cbB + 4);
        __syncthreads();
        sA[ca+0][ra] = a0.x; sA[ca+1][ra] = a0.y; sA[ca+2][ra] = a0.z; sA[ca+3][ra] = a0.w;
        sA[ca+4][ra] = a1.x; sA[ca+5][ra] = a1.y; sA[ca+6][ra] = a1.z; sA[ca+7][ra] = a1.w;
        *(float4*)&sB[kb][cbB]     = b0;
        *(float4*)&sB[kb][cbB + 4] = b1;
        __syncthreads();

#pragma unroll
        for (int kk = 0; kk < BKB; kk++) {
            float4 av0 = *(const float4*)&sA[kk][ty * 8];
            float4 av1 = *(const float4*)&sA[kk][ty * 8 + 4];
            float4 bv0 = *(const float4*)&sB[kk][tx * 8];
            float4 bv1 = *(const float4*)&sB[kk][tx * 8 + 4];
            unsigned long long b01 = pack2(bv0.x, bv0.y), b23 = pack2(bv0.z, bv0.w);
            unsigned long long b45 = pack2(bv1.x, bv1.y), b67 = pack2(bv1.z, bv1.w);
            float a[8] = {av0.x, av0.y, av0.z, av0.w, av1.x, av1.y, av1.z, av1.w};
#pragma unroll
            for (int i = 0; i < 8; i++) {
                unsigned long long aa = pack2(a[i], a[i]);
                ffma2(acc[i][0], aa, b01);
                ffma2(acc[i][1], aa, b23);
                ffma2(acc[i][2], aa, b45);
                ffma2(acc[i][3], aa, b67);
            }
        }
    }

#pragma unroll
    for (int i = 0; i < 8; i++) {
        int r = ty * 8 + i;
        int entry = sTok[r];
        if (entry < 0) continue;
        float w = sW[r];
        float2 y0 = unpack2(acc[i][0]), y1 = unpack2(acc[i][1]);
        float2 y2 = unpack2(acc[i][2]), y3 = unpack2(acc[i][3]);
        float4 o0 = make_float4(w*y0.x, w*y0.y, w*y1.x, w*y1.y);
        float4 o1 = make_float4(w*y2.x, w*y2.y, w*y3.x, w*y3.y);
        float* op = g_pout + (size_t)entry * DIM + col0 + tx * 8;
        *(float4*)(op)     = o0;
        *(float4*)(op + 4) = o1;
    }
}

// ---------------- combine the two pair slots per token ----------------
__global__ void combine_kernel(float* __restrict__ out) {
    int i = blockIdx.x * blockDim.x + threadIdx.x;        // float4 index
    const int N4  = T_TOK * DIM / 4;
    const int D4  = DIM / 4;
    if (i >= N4) return;
    int t = i / D4, c = i % D4;
    const float4* p = (const float4*)g_pout;
    float4 a = p[(size_t)(2 * t) * D4 + c];
    float4 b = p[(size_t)(2 * t + 1) * D4 + c];
    ((float4*)out)[i] = make_float4(a.x + b.x, a.y + b.y, a.z + b.z, a.w + b.w);
}

// ---------------- aux loss ----------------
__global__ void finalize_kernel(float* __restrict__ out, int out_size) {
    float lb = 0.f;
#pragma unroll
    for (int e = 0; e < NE; e++)
        lb += ((float)g_cnt[e] / (float)NPAIR) * (g_sumP[e] / (float)T_TOK);
    float aux = 0.01f * (float)NE * lb + 0.001f * (g_zsum / (float)T_TOK);
    out[out_size - 1] = aux;
}

// ---------------- launch ----------------
extern "C" void kernel_launch(void* const* d_in, const int* in_sizes, int n_in,
                              void* d_out, int out_size) {
    const float* x  = (const float*)d_in[0];
    const float* rw = (const float*)d_in[1];
    const float* gw = (const float*)d_in[2];
    const float* uw = (const float*)d_in[3];
    const float* dw = (const float*)d_in[4];
    float* out = (float*)d_out;

    zero_kernel<<<1, 32>>>();
    router_kernel<<<T_TOK / 4, 128>>>(x, rw);
    gateup_kernel<<<dim3(FDIM / BNA, T_TOK / BMA, NE), 256>>>(x, gw, uw);
    down_kernel<<<dim3(DIM / BNB, T_TOK / BMB, NE), 256>>>(dw);
    combine_kernel<<<(T_TOK * DIM / 4 + 255) / 256, 256>>>(out);
    finalize_kernel<<<1, 1>>>(out, out_size);
}

// round 4
// speedup vs baseline: 1.0524x; 1.0524x over previous
#include <cuda_runtime.h>
#include <math.h>

// Problem constants (fixed shapes)
#define T_TOK 4096
#define DIM   512
#define FDIM  1024
#define NE    8
#define TOPK  2
#define NPAIR (T_TOK*TOPK)

// ---------------- device scratch (static; no runtime allocation) ----------------
__device__ int   g_cnt[NE];
__device__ int   g_list[NE*T_TOK];   // packed (token<<1)|k
__device__ float g_wgt [NE*T_TOK];   // normalized top-k weight for that pair
__device__ float g_sumP[NE];
__device__ float g_zsum;
__device__ float g_hidden[(size_t)NPAIR*FDIM];  // silu(g)*u per pair  (33.5 MB)
__device__ float g_pout [(size_t)NPAIR*DIM];    // per-pair down-proj   (16.8 MB)

// ---------------- f32x2 packed-FMA helpers (sm_100+ PTX) ----------------
__device__ __forceinline__ unsigned long long pack2(float lo, float hi) {
    unsigned long long r;
    asm("mov.b64 %0, {%1, %2};" : "=l"(r) : "f"(lo), "f"(hi));
    return r;
}
__device__ __forceinline__ float2 unpack2(unsigned long long v) {
    float2 r;
    asm("mov.b64 {%0, %1}, %2;" : "=f"(r.x), "=f"(r.y) : "l"(v));
    return r;
}
__device__ __forceinline__ void ffma2(unsigned long long& acc,
                                      unsigned long long a, unsigned long long b) {
    asm("fma.rn.f32x2 %0, %1, %2, %0;" : "+l"(acc) : "l"(a), "l"(b));
}

// ---------------- zero per-launch accumulators ----------------
__global__ void zero_kernel() {
    int i = threadIdx.x;
    if (i < NE) { g_cnt[i] = 0; g_sumP[i] = 0.f; }
    if (i == 0) g_zsum = 0.f;
}

// ---------------- router: logits, softmax, top-2, lists, aux sums ----------------
__global__ void router_kernel(const float* __restrict__ x, const float* __restrict__ rw) {
    int gw   = (blockIdx.x * blockDim.x + threadIdx.x) >> 5;   // token
    int lane = threadIdx.x & 31;
    if (gw >= T_TOK) return;

    const float4* xp = (const float4*)(x + (size_t)gw * DIM);
    float4 xv[4];
#pragma unroll
    for (int i = 0; i < 4; i++) xv[i] = xp[lane * 4 + i];

    float logit[NE];
#pragma unroll
    for (int e = 0; e < NE; e++) {
        const float4* wp = (const float4*)(rw + (size_t)e * DIM);
        float acc = 0.f;
#pragma unroll
        for (int i = 0; i < 4; i++) {
            float4 w4 = wp[lane * 4 + i];
            acc += xv[i].x * w4.x + xv[i].y * w4.y + xv[i].z * w4.z + xv[i].w * w4.w;
        }
#pragma unroll
        for (int o = 16; o > 0; o >>= 1) acc += __shfl_xor_sync(0xffffffffu, acc, o);
        logit[e] = acc;
    }

    if (lane == 0) {
        float m = logit[0];
#pragma unroll
        for (int e = 1; e < NE; e++) m = fmaxf(m, logit[e]);
        float p[NE]; float se = 0.f;
#pragma unroll
        for (int e = 0; e < NE; e++) { p[e] = expf(logit[e] - m); se += p[e]; }
        float inv = 1.f / se;

        int i0 = 0; float v0 = -1.f;
#pragma unroll
        for (int e = 0; e < NE; e++) if (p[e] > v0) { v0 = p[e]; i0 = e; }
        int i1 = -1; float v1 = -1.f;
#pragma unroll
        for (int e = 0; e < NE; e++) if (e != i0 && p[e] > v1) { v1 = p[e]; i1 = e; }

        float s2 = v0 + v1;
        float w0 = v0 / s2, w1 = v1 / s2;

        int pos0 = atomicAdd(&g_cnt[i0], 1);
        g_list[i0 * T_TOK + pos0] = (gw << 1);
        g_wgt [i0 * T_TOK + pos0] = w0;
        int pos1 = atomicAdd(&g_cnt[i1], 1);
        g_list[i1 * T_TOK + pos1] = (gw << 1) | 1;
        g_wgt [i1 * T_TOK + pos1] = w1;

#pragma unroll
        for (int e = 0; e < NE; e++) atomicAdd(&g_sumP[e], p[e] * inv);
        float lse = m + logf(se);
        atomicAdd(&g_zsum, lse * lse);
    }
}

// ---------------- phase A: hidden = silu(Xe@gate) * (Xe@up), gathered rows ----------------
#define BMA 128
#define BNA 64
#define BKA 16
__global__ void __launch_bounds__(256) gateup_kernel(const float* __restrict__ x,
                                                     const float* __restrict__ gw,
                                                     const float* __restrict__ uw) {
    int e = blockIdx.z;
    int cnt = g_cnt[e];
    int row0 = blockIdx.y * BMA;
    if (row0 >= cnt) return;
    int col0 = blockIdx.x * BNA;

    __shared__ __align__(16) float sA [BKA][BMA];
    __shared__ __align__(16) float sBg[BKA][BNA];
    __shared__ __align__(16) float sBu[BKA][BNA];
    __shared__ int sTok[BMA];

    int tid = threadIdx.x;
    for (int i = tid; i < BMA; i += 256) {
        int r = row0 + i;
        sTok[i] = (r < cnt) ? g_list[e * T_TOK + r] : -1;
    }
    __syncthreads();

    int tx = tid & 15, ty = tid >> 4;
    unsigned long long accg[8][2], accu[8][2];
#pragma unroll
    for (int i = 0; i < 8; i++) {
        accg[i][0] = accg[i][1] = 0ull;
        accu[i][0] = accu[i][1] = 0ull;
    }

    const float* gbase = gw + (size_t)e * DIM * FDIM + col0;
    const float* ubase = uw + (size_t)e * DIM * FDIM + col0;

    int ra = tid >> 1;           // 0..127  A row
    int ca = (tid & 1) * 8;      // 0 / 8   A col block
    int entryA = sTok[ra];
    const float* xrow = (entryA >= 0) ? (x + (size_t)(entryA >> 1) * DIM) : x;
    int kb  = tid >> 4;          // 0..15   B row
    int cb  = (tid & 15) * 4;    // B col

    for (int kt = 0; kt < DIM; kt += BKA) {
        float4 a0, a1;
        if (entryA >= 0) {
            a0 = *(const float4*)(xrow + kt + ca);
            a1 = *(const float4*)(xrow + kt + ca + 4);
        } else {
            a0 = make_float4(0.f,0.f,0.f,0.f); a1 = a0;
        }
        float4 bg4 = *(const float4*)(gbase + (size_t)(kt + kb) * FDIM + cb);
        float4 bu4 = *(const float4*)(ubase + (size_t)(kt + kb) * FDIM + cb);
        __syncthreads();
        sA[ca+0][ra] = a0.x; sA[ca+1][ra] = a0.y; sA[ca+2][ra] = a0.z; sA[ca+3][ra] = a0.w;
        sA[ca+4][ra] = a1.x; sA[ca+5][ra] = a1.y; sA[ca+6][ra] = a1.z; sA[ca+7][ra] = a1.w;
        *(float4*)&sBg[kb][cb] = bg4;
        *(float4*)&sBu[kb][cb] = bu4;
        __syncthreads();

#pragma unroll
        for (int kk = 0; kk < BKA; kk++) {
            float4 av0 = *(const float4*)&sA[kk][ty * 8];
            float4 av1 = *(const float4*)&sA[kk][ty * 8 + 4];
            float4 bg  = *(const float4*)&sBg[kk][tx * 4];
            float4 bu  = *(const float4*)&sBu[kk][tx * 4];
            unsigned long long bg01 = pack2(bg.x, bg.y), bg23 = pack2(bg.z, bg.w);
            unsigned long long bu01 = pack2(bu.x, bu.y), bu23 = pack2(bu.z, bu.w);
            float a[8] = {av0.x, av0.y, av0.z, av0.w, av1.x, av1.y, av1.z, av1.w};
#pragma unroll
            for (int i = 0; i < 8; i++) {
                unsigned long long aa = pack2(a[i], a[i]);
                ffma2(accg[i][0], aa, bg01);
                ffma2(accg[i][1], aa, bg23);
                ffma2(accu[i][0], aa, bu01);
                ffma2(accu[i][1], aa, bu23);
            }
        }
    }

#pragma unroll
    for (int i = 0; i < 8; i++) {
        int r = ty * 8 + i;
        int entry = sTok[r];
        if (entry < 0) continue;
        float2 g0 = unpack2(accg[i][0]), g1 = unpack2(accg[i][1]);
        float2 u0 = unpack2(accu[i][0]), u1 = unpack2(accu[i][1]);
        float4 h;
        h.x = u0.x * (g0.x / (1.f + expf(-g0.x)));
        h.y = u0.y * (g0.y / (1.f + expf(-g0.y)));
        h.z = u1.x * (g1.x / (1.f + expf(-g1.x)));
        h.w = u1.y * (g1.y / (1.f + expf(-g1.y)));
        *(float4*)(g_hidden + (size_t)entry * FDIM + col0 + tx * 4) = h;
    }
}

// ---------------- phase B: pair_out = w * (hidden @ down) ----------------
#define BMB 128
#define BNB 128
#define BKB 16
__global__ void __launch_bounds__(256) down_kernel(const float* __restrict__ dw) {
    int e = blockIdx.z;
    int cnt = g_cnt[e];
    int row0 = blockIdx.y * BMB;
    if (row0 >= cnt) return;
    int col0 = blockIdx.x * BNB;

    __shared__ __align__(16) float sA[BKB][BMB];
    __shared__ __align__(16) float sB[BKB][BNB];
    __shared__ int   sTok[BMB];
    __shared__ float sW  [BMB];

    int tid = threadIdx.x;
    for (int i = tid; i < BMB; i += 256) {
        int r = row0 + i;
        sTok[i] = (r < cnt) ? g_list[e * T_TOK + r] : -1;
        sW[i]   = (r < cnt) ? g_wgt [e * T_TOK + r] : 0.f;
    }
    __syncthreads();

    int tx = tid & 15, ty = tid >> 4;
    unsigned long long acc[8][4];
#pragma unroll
    for (int i = 0; i < 8; i++)
#pragma unroll
        for (int j = 0; j < 4; j++) acc[i][j] = 0ull;

    int ra = tid >> 1;         // A row
    int ca = (tid & 1) * 8;
    int entryA = sTok[ra];
    const float* hrow = (entryA >= 0) ? (g_hidden + (size_t)entryA * FDIM) : g_hidden;
    int kb  = tid >> 4;        // 0..15 B row
    int cbB = (tid & 15) * 8;  // B col
    const float* dbase = dw + (size_t)e * FDIM * DIM + col0;

    for (int kt = 0; kt < FDIM; kt += BKB) {
        float4 a0, a1;
        if (entryA >= 0) {
            a0 = *(const float4*)(hrow + kt + ca);
            a1 = *(const float4*)(hrow + kt + ca + 4);
        } else {
            a0 = make_float4(0.f,0.f,0.f,0.f); a1 = a0;
        }
        float4 b0 = *(const float4*)(dbase + (size_t)(kt + kb) * DIM + cbB);
        float4 b1 = *(const float4*)(dbase + (size_t)(kt + kb) * DIM + cbB + 4);
        __syncthreads();
        sA[ca+0][ra] = a0.x; sA[ca+1][ra] = a0.y; sA[ca+2][ra] = a0.z; sA[ca+3][ra] = a0.w;
        sA[ca+4][ra] = a1.x; sA[ca+5][ra] = a1.y; sA[ca+6][ra] = a1.z; sA[ca+7][ra] = a1.w;
        *(float4*)&sB[kb][cbB]     = b0;
        *(float4*)&sB[kb][cbB + 4] = b1;
        __syncthreads();

#pragma unroll
        for (int kk = 0; kk < BKB; kk++) {
            float4 av0 = *(const float4*)&sA[kk][ty * 8];
            float4 av1 = *(const float4*)&sA[kk][ty * 8 + 4];
            float4 bv0 = *(const float4*)&sB[kk][tx * 8];
            float4 bv1 = *(const float4*)&sB[kk][tx * 8 + 4];
            unsigned long long b01 = pack2(bv0.x, bv0.y), b23 = pack2(bv0.z, bv0.w);
            unsigned long long b45 = pack2(bv1.x, bv1.y), b67 = pack2(bv1.z, bv1.w);
            float a[8] = {av0.x, av0.y, av0.z, av0.w, av1.x, av1.y, av1.z, av1.w};
#pragma unroll
            for (int i = 0; i < 8; i++) {
                unsigned long long aa = pack2(a[i], a[i]);
                ffma2(acc[i][0], aa, b01);
                ffma2(acc[i][1], aa, b23);
                ffma2(acc[i][2], aa, b45);
                ffma2(acc[i][3], aa, b67);
            }
        }
    }

#pragma unroll
    for (int i = 0; i < 8; i++) {
        int r = ty * 8 + i;
        int entry = sTok[r];
        if (entry < 0) continue;
        float w = sW[r];
        float2 y0 = unpack2(acc[i][0]), y1 = unpack2(acc[i][1]);
        float2 y2 = unpack2(acc[i][2]), y3 = unpack2(acc[i][3]);
        float4 o0 = make_float4(w*y0.x, w*y0.y, w*y1.x, w*y1.y);
        float4 o1 = make_float4(w*y2.x, w*y2.y, w*y3.x, w*y3.y);
        float* op = g_pout + (size_t)entry * DIM + col0 + tx * 8;
        *(float4*)(op)     = o0;
        *(float4*)(op + 4) = o1;
    }
}

// ---------------- combine the two pair slots per token ----------------
__global__ void combine_kernel(float* __restrict__ out) {
    int i = blockIdx.x * blockDim.x + threadIdx.x;        // float4 index
    const int N4  = T_TOK * DIM / 4;
    const int D4  = DIM / 4;
    if (i >= N4) return;
    int t = i / D4, c = i % D4;
    const float4* p = (const float4*)g_pout;
    float4 a = p[(size_t)(2 * t) * D4 + c];
    float4 b = p[(size_t)(2 * t + 1) * D4 + c];
    ((float4*)out)[i] = make_float4(a.x + b.x, a.y + b.y, a.z + b.z, a.w + b.w);
}

// ---------------- aux loss ----------------
__global__ void finalize_kernel(float* __restrict__ out, int out_size) {
    float lb = 0.f;
#pragma unroll
    for (int e = 0; e < NE; e++)
        lb += ((float)g_cnt[e] / (float)NPAIR) * (g_sumP[e] / (float)T_TOK);
    float aux = 0.01f * (float)NE * lb + 0.001f * (g_zsum / (float)T_TOK);
    out[out_size - 1] = aux;
}

// ---------------- launch ----------------
extern "C" void kernel_launch(void* const* d_in, const int* in_sizes, int n_in,
                              void* d_out, int out_size) {
    const float* x  = (const float*)d_in[0];
    const float* rw = (const float*)d_in[1];
    const float* gw = (const float*)d_in[2];
    const float* uw = (const float*)d_in[3];
    const float* dw = (const float*)d_in[4];
    float* out = (float*)d_out;

    zero_kernel<<<1, 32>>>();
    router_kernel<<<T_TOK / 4, 128>>>(x, rw);
    gateup_kernel<<<dim3(FDIM / BNA, T_TOK / BMA, NE), 256>>>(x, gw, uw);
    down_kernel<<<dim3(DIM / BNB, T_TOK / BMB, NE), 256>>>(dw);
    combine_kernel<<<(T_TOK * DIM / 4 + 255) / 256, 256>>>(out);
    finalize_kernel<<<1, 1>>>(out, out_size);
}